// round 1
// baseline (speedup 1.0000x reference)
#include <cuda_runtime.h>
#include <math.h>

#define N_STATES 2048
#define NMASK    2047
#define V_TOK    10000
#define B_       4
#define T_       16
#define L_       16

// scratch: emis[b][t][n] = sum_l E_ls[n, tok[b,t,l]]  (log-emission sums)
__device__ float g_emis[B_ * T_ * N_STATES];

// ---------------------------------------------------------------------------
// Kernel 1: per-state-row logsumexp over V, plus gathered token sums.
// One block per state row n. Two passes over the 40KB row (2nd pass L1/L2 hit).
// ---------------------------------------------------------------------------
__global__ void __launch_bounds__(256) emis_kernel(const float* __restrict__ Ew,
                                                   const int* __restrict__ stories)
{
    const int n   = blockIdx.x;
    const int tid = threadIdx.x;
    const float* __restrict__ row = Ew + (size_t)n * V_TOK;
    const float4* __restrict__ row4 = (const float4*)row;   // row base is 16B aligned (n*40000)

    __shared__ int   s_tok[B_ * T_ * L_];
    __shared__ float s_red[32];
    __shared__ float s_lse;

    for (int i = tid; i < B_ * T_ * L_; i += 256) s_tok[i] = stories[i];

    // ---- pass 1: row max ----
    float m = -INFINITY;
    for (int i = tid; i < V_TOK / 4; i += 256) {
        float4 v = row4[i];
        m = fmaxf(m, fmaxf(fmaxf(v.x, v.y), fmaxf(v.z, v.w)));
    }
    #pragma unroll
    for (int o = 16; o > 0; o >>= 1) m = fmaxf(m, __shfl_xor_sync(0xFFFFFFFFu, m, o));
    if ((tid & 31) == 0) s_red[tid >> 5] = m;
    __syncthreads();
    if (tid < 32) {
        float mm = (tid < 8) ? s_red[tid] : -INFINITY;
        #pragma unroll
        for (int o = 4; o > 0; o >>= 1) mm = fmaxf(mm, __shfl_xor_sync(0xFFFFFFFFu, mm, o));
        if (tid == 0) s_red[0] = mm;
    }
    __syncthreads();
    const float M = s_red[0];
    __syncthreads();

    // ---- pass 2: sum exp(x - M) ----
    float s = 0.f;
    for (int i = tid; i < V_TOK / 4; i += 256) {
        float4 v = row4[i];
        s += __expf(v.x - M) + __expf(v.y - M) + __expf(v.z - M) + __expf(v.w - M);
    }
    #pragma unroll
    for (int o = 16; o > 0; o >>= 1) s += __shfl_xor_sync(0xFFFFFFFFu, s, o);
    if ((tid & 31) == 0) s_red[tid >> 5] = s;
    __syncthreads();
    if (tid < 32) {
        float ss = (tid < 8) ? s_red[tid] : 0.f;
        #pragma unroll
        for (int o = 4; o > 0; o >>= 1) ss += __shfl_xor_sync(0xFFFFFFFFu, ss, o);
        if (tid == 0) s_lse = M + __logf(ss);
    }
    __syncthreads();
    const float lse = s_lse;

    // ---- gather: 64 (b,t) pairs, 16 tokens each (row is hot in L1/L2) ----
    if (tid < B_ * T_) {
        const int* tk = s_tok + tid * L_;
        float g = 0.f;
        #pragma unroll
        for (int l = 0; l < L_; l++) g += __ldg(row + tk[l]);
        g_emis[tid * N_STATES + n] = g - (float)L_ * lse;
    }
}

// ---------------------------------------------------------------------------
// Kernel 2: forward recurrence. One block per batch story; alpha + transition
// coefficients live in shared memory; 16 sequential timesteps.
//
// Transition band: cols = (h - delta) % N for deltas {0,1,-1,32,-32,1024,2048}.
// N=2048 so delta=2048 aliases delta=0 (diagonal); scatter-set applies updates
// in order, so slot 6 wins on the diagonal and slot 0 is dead.
// ---------------------------------------------------------------------------
__global__ void __launch_bounds__(1024) forward_kernel(
    const float* __restrict__ trans_w,
    const float* __restrict__ prior_w,
    float* __restrict__ out)
{
    extern __shared__ float sm[];
    float* tc   = sm;                      // [6][N] stencil coefficients
    float* abuf = sm + 6 * N_STATES;       // [2][N] alpha double buffer
    __shared__ float s_red[32];
    __shared__ float s_plse;

    const int b   = blockIdx.x;
    const int tid = threadIdx.x;

    // ---- transition log-softmax over 7 slots, keep slots {6,1,2,3,4,5} ----
    for (int h = tid; h < N_STATES; h += 1024) {
        float w[7];
        #pragma unroll
        for (int j = 0; j < 7; j++) w[j] = trans_w[h * 7 + j];
        float m = w[0];
        #pragma unroll
        for (int j = 1; j < 7; j++) m = fmaxf(m, w[j]);
        float s = 0.f;
        #pragma unroll
        for (int j = 0; j < 7; j++) s += __expf(w[j] - m);
        const float lse = m + __logf(s);
        tc[0 * N_STATES + h] = w[6] - lse;   // diagonal (slot 6 wins over slot 0)
        tc[1 * N_STATES + h] = w[1] - lse;   // from (h-1)
        tc[2 * N_STATES + h] = w[2] - lse;   // from (h+1)
        tc[3 * N_STATES + h] = w[3] - lse;   // from (h-32)
        tc[4 * N_STATES + h] = w[4] - lse;   // from (h+32)
        tc[5 * N_STATES + h] = w[5] - lse;   // from (h-1024)
    }

    // ---- prior logsumexp (block reduce over 2048) ----
    float pm = -INFINITY;
    for (int h = tid; h < N_STATES; h += 1024) pm = fmaxf(pm, prior_w[h]);
    #pragma unroll
    for (int o = 16; o > 0; o >>= 1) pm = fmaxf(pm, __shfl_xor_sync(0xFFFFFFFFu, pm, o));
    if ((tid & 31) == 0) s_red[tid >> 5] = pm;
    __syncthreads();
    if (tid < 32) {
        float mm = s_red[tid];
        #pragma unroll
        for (int o = 16; o > 0; o >>= 1) mm = fmaxf(mm, __shfl_xor_sync(0xFFFFFFFFu, mm, o));
        if (tid == 0) s_red[0] = mm;
    }
    __syncthreads();
    const float PM = s_red[0];
    __syncthreads();

    float ps = 0.f;
    for (int h = tid; h < N_STATES; h += 1024) ps += __expf(prior_w[h] - PM);
    #pragma unroll
    for (int o = 16; o > 0; o >>= 1) ps += __shfl_xor_sync(0xFFFFFFFFu, ps, o);
    if ((tid & 31) == 0) s_red[tid >> 5] = ps;
    __syncthreads();
    if (tid < 32) {
        float ss = s_red[tid];
        #pragma unroll
        for (int o = 16; o > 0; o >>= 1) ss += __shfl_xor_sync(0xFFFFFFFFu, ss, o);
        if (tid == 0) s_plse = PM + __logf(ss);
    }
    __syncthreads();
    const float plse = s_plse;

    // ---- alpha0 ----
    const float* __restrict__ emisb = g_emis + (size_t)b * T_ * N_STATES;
    for (int h = tid; h < N_STATES; h += 1024) {
        const float a = emisb[h] + prior_w[h] - plse;
        abuf[h] = a;
        out[(size_t)0 * B_ * N_STATES + b * N_STATES + h] = a;
    }
    __syncthreads();

    // ---- recurrence: 6-neighbor stencil logsumexp per step ----
    int cur = 0;
    for (int t = 1; t < T_; t++) {
        const float* __restrict__ ao = abuf + cur * N_STATES;
        float* __restrict__       an = abuf + (cur ^ 1) * N_STATES;
        for (int h = tid; h < N_STATES; h += 1024) {
            const float v0 = ao[h]                  + tc[0 * N_STATES + h];
            const float v1 = ao[(h - 1)    & NMASK] + tc[1 * N_STATES + h];
            const float v2 = ao[(h + 1)    & NMASK] + tc[2 * N_STATES + h];
            const float v3 = ao[(h - 32)   & NMASK] + tc[3 * N_STATES + h];
            const float v4 = ao[(h + 32)   & NMASK] + tc[4 * N_STATES + h];
            const float v5 = ao[(h - 1024) & NMASK] + tc[5 * N_STATES + h];
            const float m  = fmaxf(fmaxf(fmaxf(v0, v1), fmaxf(v2, v3)), fmaxf(v4, v5));
            const float s  = __expf(v0 - m) + __expf(v1 - m) + __expf(v2 - m) +
                             __expf(v3 - m) + __expf(v4 - m) + __expf(v5 - m);
            const float a  = emisb[t * N_STATES + h] + m + __logf(s);
            an[h] = a;
            out[(size_t)t * B_ * N_STATES + b * N_STATES + h] = a;
        }
        cur ^= 1;
        __syncthreads();
    }
}

// ---------------------------------------------------------------------------
extern "C" void kernel_launch(void* const* d_in, const int* in_sizes, int n_in,
                              void* d_out, int out_size)
{
    // identify inputs by element count (all distinct):
    // stories 1024, story_length 1, transition_w 14336, emission_w 20480000, prior 2048
    const int*   stories = nullptr;
    const float* trans_w = nullptr;
    const float* emis_w  = nullptr;
    const float* prior_w = nullptr;
    for (int i = 0; i < n_in; i++) {
        switch (in_sizes[i]) {
            case B_ * T_ * L_:          stories = (const int*)d_in[i];   break;
            case N_STATES * 7:          trans_w = (const float*)d_in[i]; break;
            case N_STATES * V_TOK:      emis_w  = (const float*)d_in[i]; break;
            case N_STATES:              prior_w = (const float*)d_in[i]; break;
            default: break; // story_length scalar unused (T_ compile-time)
        }
    }
    float* out = (float*)d_out;

    emis_kernel<<<N_STATES, 256>>>(emis_w, stories);

    const int smem = (6 + 2) * N_STATES * (int)sizeof(float); // 64 KB
    static bool attr_set = false;
    if (!attr_set) {
        cudaFuncSetAttribute(forward_kernel,
                             cudaFuncAttributeMaxDynamicSharedMemorySize, smem);
        attr_set = true;
    }
    forward_kernel<<<B_, 1024, smem>>>(trans_w, prior_w, out);
}